// round 14
// baseline (speedup 1.0000x reference)
#include <cuda_runtime.h>
#include <cuda_fp16.h>

// out[e] = sigmoid( dot( x[src[e], 0:128], x[dst[e], 128:256] ) )
// x: [100000, 256] fp32. edge_label_index: [2, N_EDGES] int32 on device.
//
// Two kernels per launch:
//  1) convert x (102 MB fp32) -> static __device__ fp16 table (51.2 MB).
//     fp32 reads evict_first, fp16 writes evict_last. Runs at the 153 MB
//     streaming floor (~14 us).
//  2) gather: 8 edges/warp, per-lane uint2 (4 halves) per half-row.
//     Per-lane partial dot via HMUL2+HFMA2 (2 ops, fp16; only 2 products
//     per slot before fp32 conversion), then fp32 merging butterfly.

#define N_NODES 100000
#define HIDDEN  256
#define HALF    128
#define EPW     8     // edges per warp

__device__ static __half g_xh[(size_t)N_NODES * HIDDEN];   // 51.2 MB scratch

__device__ __forceinline__ float sigmoidf(float v)
{
    return __fdividef(1.0f, 1.0f + __expf(-v));
}

__device__ __forceinline__ unsigned long long pol_evict_first()
{
    unsigned long long p;
    asm("createpolicy.fractional.L2::evict_first.b64 %0, 1.0;" : "=l"(p));
    return p;
}
__device__ __forceinline__ unsigned long long pol_evict_last()
{
    unsigned long long p;
    asm("createpolicy.fractional.L2::evict_last.b64 %0, 1.0;" : "=l"(p));
    return p;
}

// ---------------- kernel 1: fp32 -> fp16 table ----------------
__global__ __launch_bounds__(256)
void convert_kernel(const float* __restrict__ x, int n8)
{
    int i = blockIdx.x * blockDim.x + threadIdx.x;
    if (i >= n8) return;

    unsigned long long pf = pol_evict_first();
    unsigned long long pl = pol_evict_last();

    const float4* src = reinterpret_cast<const float4*>(x) + 2 * i;
    float4 v0, v1;
    asm("ld.global.nc.L2::cache_hint.v4.f32 {%0,%1,%2,%3}, [%4], %5;"
        : "=f"(v0.x), "=f"(v0.y), "=f"(v0.z), "=f"(v0.w) : "l"(src), "l"(pf));
    asm("ld.global.nc.L2::cache_hint.v4.f32 {%0,%1,%2,%3}, [%4], %5;"
        : "=f"(v1.x), "=f"(v1.y), "=f"(v1.z), "=f"(v1.w) : "l"(src + 1), "l"(pf));

    __half2 h0 = __floats2half2_rn(v0.x, v0.y);
    __half2 h1 = __floats2half2_rn(v0.z, v0.w);
    __half2 h2 = __floats2half2_rn(v1.x, v1.y);
    __half2 h3 = __floats2half2_rn(v1.z, v1.w);
    unsigned u0 = *reinterpret_cast<unsigned*>(&h0);
    unsigned u1 = *reinterpret_cast<unsigned*>(&h1);
    unsigned u2 = *reinterpret_cast<unsigned*>(&h2);
    unsigned u3 = *reinterpret_cast<unsigned*>(&h3);

    uint4* dst = reinterpret_cast<uint4*>(g_xh) + i;
    asm volatile("st.global.L2::cache_hint.v4.b32 [%0], {%1,%2,%3,%4}, %5;"
                 :: "l"(dst), "r"(u0), "r"(u1), "r"(u2), "r"(u3), "l"(pl)
                 : "memory");
}

// dot of 4 halves vs 4 halves: HMUL2 + HFMA2 in fp16 (2 products per slot),
// then one conversion to fp32 and a scalar add.
__device__ __forceinline__ float dot4h(uint2 ua, uint2 ub)
{
    __half2 a0 = *reinterpret_cast<__half2*>(&ua.x);
    __half2 a1 = *reinterpret_cast<__half2*>(&ua.y);
    __half2 b0 = *reinterpret_cast<__half2*>(&ub.x);
    __half2 b1 = *reinterpret_cast<__half2*>(&ub.y);
    __half2 p = __hmul2(a0, b0);
    p = __hfma2(a1, b1, p);
    float2 f = __half22float2(p);
    return f.x + f.y;
}

// ---------------- kernel 2: edge gather + dot + sigmoid ----------------
__global__ __launch_bounds__(256)
void edge_dot_sigmoid_kernel(const int* __restrict__ eidx,
                             float* __restrict__ out,
                             int n_edges)
{
    int warp = (blockIdx.x * blockDim.x + threadIdx.x) >> 5;
    int lane = threadIdx.x & 31;
    int base = warp * EPW;
    if (base >= n_edges) return;

    if (base + EPW <= n_edges) {
        // Warp-uniform vector index loads (16B requests).
        int4 s0 = __ldg(reinterpret_cast<const int4*>(eidx + base));
        int4 s1 = __ldg(reinterpret_cast<const int4*>(eidx + base + 4));
        int4 d0 = __ldg(reinterpret_cast<const int4*>(eidx + n_edges + base));
        int4 d1 = __ldg(reinterpret_cast<const int4*>(eidx + n_edges + base + 4));
        int s[EPW] = {s0.x, s0.y, s0.z, s0.w, s1.x, s1.y, s1.z, s1.w};
        int d[EPW] = {d0.x, d0.y, d0.z, d0.w, d1.x, d1.y, d1.z, d1.w};

        // Issue all 16 LDG.64 gathers before any math (MLP=16 per lane).
        uint2 a[EPW], b[EPW];
        #pragma unroll
        for (int k = 0; k < EPW; k++)
            a[k] = __ldg(reinterpret_cast<const uint2*>(
                       g_xh + (long long)s[k] * HIDDEN) + lane);
        #pragma unroll
        for (int k = 0; k < EPW; k++)
            b[k] = __ldg(reinterpret_cast<const uint2*>(
                       g_xh + (long long)d[k] * HIDDEN + HALF) + lane);

        float v[EPW];
        #pragma unroll
        for (int k = 0; k < EPW; k++)
            v[k] = dot4h(a[k], b[k]);

        // Merging butterfly: 8 -> 4 -> 2 -> 1 arrays, then finish the tree.
        float m0[4];
        #pragma unroll
        for (int k = 0; k < 4; k++) {
            float e0 = v[2*k]   + __shfl_xor_sync(0xffffffffu, v[2*k],   1);
            float e1 = v[2*k+1] + __shfl_xor_sync(0xffffffffu, v[2*k+1], 1);
            m0[k] = (lane & 1) ? e1 : e0;
        }
        float m1[2];
        #pragma unroll
        for (int k = 0; k < 2; k++) {
            float e0 = m0[2*k]   + __shfl_xor_sync(0xffffffffu, m0[2*k],   2);
            float e1 = m0[2*k+1] + __shfl_xor_sync(0xffffffffu, m0[2*k+1], 2);
            m1[k] = (lane & 2) ? e1 : e0;
        }
        float e0 = m1[0] + __shfl_xor_sync(0xffffffffu, m1[0], 4);
        float e1 = m1[1] + __shfl_xor_sync(0xffffffffu, m1[1], 4);
        float m2 = (lane & 4) ? e1 : e0;
        m2 += __shfl_xor_sync(0xffffffffu, m2, 8);
        m2 += __shfl_xor_sync(0xffffffffu, m2, 16);
        // lane l now holds the full dot for edge (l & 7).

        if (lane < EPW)
            out[base + lane] = sigmoidf(m2);
    } else {
        // Tail: up to EPW-1 edges, scalar path.
        for (int e = base; e < n_edges; e++) {
            int s = __ldg(&eidx[e]);
            int d = __ldg(&eidx[n_edges + e]);
            uint2 ua = __ldg(reinterpret_cast<const uint2*>(
                           g_xh + (long long)s * HIDDEN) + lane);
            uint2 ub = __ldg(reinterpret_cast<const uint2*>(
                           g_xh + (long long)d * HIDDEN + HALF) + lane);
            float dot = dot4h(ua, ub);
            #pragma unroll
            for (int off = 16; off > 0; off >>= 1)
                dot += __shfl_xor_sync(0xffffffffu, dot, off);
            if (lane == 0)
                out[e] = sigmoidf(dot);
        }
    }
}

extern "C" void kernel_launch(void* const* d_in, const int* in_sizes, int n_in,
                              void* d_out, int out_size)
{
    const float* x    = (const float*)d_in[0];
    const int*   eidx = (const int*)d_in[1];
    float*       out  = (float*)d_out;

    int n_x     = in_sizes[0];       // 25.6M floats (divisible by 8)
    int n_edges = in_sizes[1] / 2;   // edge_label_index has 2*N_EDGES elements

    // Kernel 1: convert table to fp16 (8 floats per thread).
    int n8 = n_x / 8;
    convert_kernel<<<(n8 + 255) / 256, 256>>>(x, n8);

    // Kernel 2: gather + dot + sigmoid.
    const int threads = 256;                       // 8 warps/block
    int warps_per_block = threads / 32;
    int edges_per_block = warps_per_block * EPW;
    int blocks = (n_edges + edges_per_block - 1) / edges_per_block;
    edge_dot_sigmoid_kernel<<<blocks, threads>>>(eidx, out, n_edges);
}